// round 16
// baseline (speedup 1.0000x reference)
#include <cuda_runtime.h>
#include <math.h>

#define BATCH 32
#define CIN 512
#define HID 64
#define PLANE 4096
#define PLANE4 1024
#define NBASE 8
#define NPLANES (BATCH * CIN)     // 16384

// Uniform grid: h = 12/5 = 2.4, t0 = -6 - 3h = -13.2
#define KNOT_T0   (-13.2f)
#define KNOT_INVH (1.0f / 2.4f)

// Scratch (no device allocations allowed)
__device__ float  g_mean[NPLANES];
__device__ float  g_h2silu[BATCH * HID];
__device__ float4 g_b2[BATCH * HID * 2];
__device__ unsigned int g_cnt[BATCH];   // per-batch completion counters (self-resetting)

__device__ __forceinline__ float siluf(float v) {
    return v / (1.0f + __expf(-v));
}

// One uniform cubic B-spline basis: q(clamp(u-j,0,4)); exactly matches the
// reference Cox-de Boor recursion on make_grid's uniform knots.
__device__ __forceinline__ float ubasis(float u, float j) {
    float v = fminf(fmaxf(u - j, 0.0f), 4.0f);
    float m1 = fmaxf(v - 1.0f, 0.0f);
    float m2 = fmaxf(v - 2.0f, 0.0f);
    float m3 = fmaxf(v - 3.0f, 0.0f);
    return (v * v * v - 4.0f * m1 * m1 * m1 + 6.0f * m2 * m2 * m2
            - 4.0f * m3 * m3 * m3) * (1.0f / 6.0f);
}

__device__ __forceinline__ float spline_dot8(float x, float4 wa, float4 wb) {
    float u = (x - KNOT_T0) * KNOT_INVH;
    return ubasis(u, 0.0f) * wa.x + ubasis(u, 1.0f) * wa.y
         + ubasis(u, 2.0f) * wa.z + ubasis(u, 3.0f) * wa.w
         + ubasis(u, 4.0f) * wb.x + ubasis(u, 5.0f) * wb.y
         + ubasis(u, 6.0f) * wb.z + ubasis(u, 7.0f) * wb.w;
}

// ---------------------------------------------------------------------------
// Kernel A: plane mean (standalone clone, reverse order) + per-batch KAN
// layer-1 tail executed by the last-finishing block of each batch.
// ---------------------------------------------------------------------------
__global__ void __launch_bounds__(256) mean_kan1_kernel(
    const float4* __restrict__ x,
    const float* __restrict__ bw1, const float* __restrict__ sw1,
    const float* __restrict__ sc1) {

    const int lane = threadIdx.x & 31;
    const int wid  = threadIdx.x >> 5;
    const int plane = NPLANES - 1 - blockIdx.x;   // reverse: tail->head
    const int b = plane >> 9;

    __shared__ float ws[8];
    __shared__ int sh_last;

    // ---- mean (exact standalone body) ----
    {
        const float4* p = x + (size_t)plane * PLANE4;
        float4 v0 = p[threadIdx.x];
        float4 v1 = p[256 + threadIdx.x];
        float4 v2 = p[512 + threadIdx.x];
        float4 v3 = p[768 + threadIdx.x];
        float sum = ((v0.x + v0.y) + (v0.z + v0.w)) + ((v1.x + v1.y) + (v1.z + v1.w))
                  + ((v2.x + v2.y) + (v2.z + v2.w)) + ((v3.x + v3.y) + (v3.z + v3.w));
#pragma unroll
        for (int off = 16; off >= 1; off >>= 1)
            sum += __shfl_xor_sync(0xffffffffu, sum, off);
        if (lane == 0) ws[wid] = sum;
        __syncthreads();
        if (threadIdx.x == 0) {
            float tot = ((ws[0] + ws[1]) + (ws[2] + ws[3]))
                      + ((ws[4] + ws[5]) + (ws[6] + ws[7]));
            float m = tot * (1.0f / (float)PLANE);
            if (isnan(m)) m = 0.0f;
            m = fminf(fmaxf(m, -3.402823466e38f), 3.402823466e38f);
            g_mean[plane] = m;
            __threadfence();
            unsigned old = atomicAdd(&g_cnt[b], 1u);
            sh_last = (old == (unsigned)(CIN - 1)) ? 1 : 0;
            if (sh_last) g_cnt[b] = 0;   // reset for next replay (sole owner now)
        }
        __syncthreads();
    }

    if (!sh_last) return;
    __threadfence();   // acquire: all batch-b means now visible

    // ---- KAN layer 1 for batch b: 8 warps x 8 outputs ----
    for (int o = wid; o < HID; o += 8) {
        const float4* sw4 = (const float4*)(sw1 + (size_t)o * CIN * NBASE);
        const float*  bwr = bw1 + o * CIN;
        const float*  scr = sc1 + o * CIN;
        float acc = 0.0f;
#pragma unroll 4
        for (int it = 0; it < 16; it++) {
            const int c = lane + 32 * it;
            float m   = g_mean[b * CIN + c];
            float4 wa = sw4[c * 2];
            float4 wb = sw4[c * 2 + 1];
            acc += siluf(m) * bwr[c] + spline_dot8(m, wa, wb) * scr[c];
        }
#pragma unroll
        for (int off = 16; off >= 1; off >>= 1)
            acc += __shfl_xor_sync(0xffffffffu, acc, off);
        if (lane == 0) {
            float h = siluf(acc);
            g_h2silu[b * HID + o] = siluf(h);
            float u = (h - KNOT_T0) * KNOT_INVH;
            float4 ba, bb;
            ba.x = ubasis(u, 0.0f); ba.y = ubasis(u, 1.0f);
            ba.z = ubasis(u, 2.0f); ba.w = ubasis(u, 3.0f);
            bb.x = ubasis(u, 4.0f); bb.y = ubasis(u, 5.0f);
            bb.z = ubasis(u, 6.0f); bb.w = ubasis(u, 7.0f);
            g_b2[(b * HID + o) * 2]     = ba;
            g_b2[(b * HID + o) * 2 + 1] = bb;
        }
    }
}

// ---------------------------------------------------------------------------
// Kernel B: inline gate (warp 0, hidden under x loads) + standalone apply.
// ---------------------------------------------------------------------------
__global__ void __launch_bounds__(256) gate_apply_kernel(
    const float4* __restrict__ x,
    const float* __restrict__ bw2, const float* __restrict__ sw2,
    const float* __restrict__ sc2,
    float4* __restrict__ out) {

    const int lane = threadIdx.x & 31;
    const int wid  = threadIdx.x >> 5;
    const int plane = blockIdx.x;            // forward: head first (L2 reuse)
    const int b = plane >> 9;
    const int c = plane & (CIN - 1);

    __shared__ float sh_g;

    // Issue x loads first (independent of gate computation).
    const float4* p = x + (size_t)plane * PLANE4;
    float4 v0 = p[threadIdx.x];
    float4 v1 = p[256 + threadIdx.x];
    float4 v2 = p[512 + threadIdx.x];
    float4 v3 = p[768 + threadIdx.x];

    // Warp 0 computes the gate while the x loads are in flight.
    if (wid == 0) {
        const int j0 = lane * 2;
        const float4* sw4 = (const float4*)(sw2 + (size_t)c * HID * NBASE);
        float4 w0 = sw4[j0 * 2];
        float4 w1 = sw4[j0 * 2 + 1];
        float4 w2 = sw4[j0 * 2 + 2];
        float4 w3 = sw4[j0 * 2 + 3];
        float4 c0 = g_b2[(b * HID + j0) * 2];
        float4 c1 = g_b2[(b * HID + j0) * 2 + 1];
        float4 c2 = g_b2[(b * HID + j0 + 1) * 2];
        float4 c3 = g_b2[(b * HID + j0 + 1) * 2 + 1];
        float sp0 = c0.x * w0.x + c0.y * w0.y + c0.z * w0.z + c0.w * w0.w
                  + c1.x * w1.x + c1.y * w1.y + c1.z * w1.z + c1.w * w1.w;
        float sp1 = c2.x * w2.x + c2.y * w2.y + c2.z * w2.z + c2.w * w2.w
                  + c3.x * w3.x + c3.y * w3.y + c3.z * w3.z + c3.w * w3.w;
        float2 bw = *(const float2*)(bw2 + c * HID + j0);
        float2 sc = *(const float2*)(sc2 + c * HID + j0);
        float2 h2 = *(const float2*)(g_h2silu + b * HID + j0);
        float acc = h2.x * bw.x + sp0 * sc.x + h2.y * bw.y + sp1 * sc.y;
#pragma unroll
        for (int off = 16; off >= 1; off >>= 1)
            acc += __shfl_xor_sync(0xffffffffu, acc, off);
        if (lane == 0) sh_g = 1.0f / (1.0f + __expf(-acc));
    }
    __syncthreads();
    const float g = sh_g;

    float4* q = out + (size_t)plane * PLANE4;
    v0.x *= g; v0.y *= g; v0.z *= g; v0.w *= g;
    v1.x *= g; v1.y *= g; v1.z *= g; v1.w *= g;
    v2.x *= g; v2.y *= g; v2.z *= g; v2.w *= g;
    v3.x *= g; v3.y *= g; v3.z *= g; v3.w *= g;
    __stcs(&q[threadIdx.x], v0);
    __stcs(&q[256 + threadIdx.x], v1);
    __stcs(&q[512 + threadIdx.x], v2);
    __stcs(&q[768 + threadIdx.x], v3);
}

extern "C" void kernel_launch(void* const* d_in, const int* in_sizes, int n_in,
                              void* d_out, int out_size) {
    const float* x     = (const float*)d_in[0];
    const float* bw1   = (const float*)d_in[2];
    const float* sw1   = (const float*)d_in[3];
    const float* sc1   = (const float*)d_in[4];
    const float* bw2   = (const float*)d_in[6];
    const float* sw2   = (const float*)d_in[7];
    const float* sc2   = (const float*)d_in[8];
    float* out = (float*)d_out;

    mean_kan1_kernel<<<NPLANES, 256>>>((const float4*)x, bw1, sw1, sc1);
    gate_apply_kernel<<<NPLANES, 256>>>((const float4*)x, bw2, sw2, sc2,
                                        (float4*)out);
}

// round 17
// speedup vs baseline: 1.1756x; 1.1756x over previous
#include <cuda_runtime.h>
#include <math.h>

#define BATCH 32
#define CIN 512
#define HID 64
#define PLANE 4096
#define PLANE4 1024
#define NBASE 8
#define NPLANES (BATCH * CIN)     // 16384

// Uniform grid: h = 12/5 = 2.4, t0 = -6 - 3h = -13.2
#define KNOT_T0   (-13.2f)
#define KNOT_INVH (1.0f / 2.4f)

// Scratch (no device allocations allowed)
__device__ float  g_mean[NPLANES];
__device__ float  g_h2silu[BATCH * HID];
__device__ float4 g_b2[BATCH * HID * 2];

__device__ __forceinline__ float siluf(float v) {
    return v / (1.0f + __expf(-v));
}

// One uniform cubic B-spline basis: q(clamp(u-j,0,4)); exactly matches the
// reference Cox-de Boor recursion on make_grid's uniform knots.
__device__ __forceinline__ float ubasis(float u, float j) {
    float v = fminf(fmaxf(u - j, 0.0f), 4.0f);
    float m1 = fmaxf(v - 1.0f, 0.0f);
    float m2 = fmaxf(v - 2.0f, 0.0f);
    float m3 = fmaxf(v - 3.0f, 0.0f);
    return (v * v * v - 4.0f * m1 * m1 * m1 + 6.0f * m2 * m2 * m2
            - 4.0f * m3 * m3 * m3) * (1.0f / 6.0f);
}

__device__ __forceinline__ float spline_dot8(float x, float4 wa, float4 wb) {
    float u = (x - KNOT_T0) * KNOT_INVH;
    return ubasis(u, 0.0f) * wa.x + ubasis(u, 1.0f) * wa.y
         + ubasis(u, 2.0f) * wa.z + ubasis(u, 3.0f) * wa.w
         + ubasis(u, 4.0f) * wb.x + ubasis(u, 5.0f) * wb.y
         + ubasis(u, 6.0f) * wb.z + ubasis(u, 7.0f) * wb.w;
}

// ---------------------------------------------------------------------------
// Kernel 1: plane mean — EXACT R1 standalone body (measured 40.4us, 85% DRAM).
// ---------------------------------------------------------------------------
__global__ void __launch_bounds__(256) mean_kernel(const float4* __restrict__ x,
                                                   float* __restrict__ s_out) {
    const int plane = blockIdx.x;
    const float4* p = x + (size_t)plane * (PLANE / 4);
    float4 v0 = p[threadIdx.x];
    float4 v1 = p[256 + threadIdx.x];
    float4 v2 = p[512 + threadIdx.x];
    float4 v3 = p[768 + threadIdx.x];
    float sum = ((v0.x + v0.y) + (v0.z + v0.w)) + ((v1.x + v1.y) + (v1.z + v1.w))
              + ((v2.x + v2.y) + (v2.z + v2.w)) + ((v3.x + v3.y) + (v3.z + v3.w));
#pragma unroll
    for (int off = 16; off >= 1; off >>= 1)
        sum += __shfl_xor_sync(0xffffffffu, sum, off);

    __shared__ float ws[8];
    if ((threadIdx.x & 31) == 0) ws[threadIdx.x >> 5] = sum;
    __syncthreads();
    if (threadIdx.x == 0) {
        float tot = ((ws[0] + ws[1]) + (ws[2] + ws[3]))
                  + ((ws[4] + ws[5]) + (ws[6] + ws[7]));
        float m = tot * (1.0f / (float)PLANE);
        if (isnan(m)) m = 0.0f;
        m = fminf(fmaxf(m, -3.402823466e38f), 3.402823466e38f);
        s_out[plane] = m;
    }
}

// ---------------------------------------------------------------------------
// Kernel 2: KAN layer 1 + layer-2 prep. One block per batch (32 blocks).
// ---------------------------------------------------------------------------
__global__ void __launch_bounds__(256) kan1_kernel(
    const float* __restrict__ bw1, const float* __restrict__ sw1,
    const float* __restrict__ sc1) {

    const int lane = threadIdx.x & 31;
    const int wid  = threadIdx.x >> 5;
    const int b = blockIdx.x;

    for (int o = wid; o < HID; o += 8) {
        const float4* sw4 = (const float4*)(sw1 + (size_t)o * CIN * NBASE);
        const float*  bwr = bw1 + o * CIN;
        const float*  scr = sc1 + o * CIN;
        float acc = 0.0f;
#pragma unroll 4
        for (int it = 0; it < 16; it++) {
            const int c = lane + 32 * it;
            float m   = g_mean[b * CIN + c];
            float4 wa = sw4[c * 2];
            float4 wb = sw4[c * 2 + 1];
            acc += siluf(m) * bwr[c] + spline_dot8(m, wa, wb) * scr[c];
        }
#pragma unroll
        for (int off = 16; off >= 1; off >>= 1)
            acc += __shfl_xor_sync(0xffffffffu, acc, off);
        if (lane == 0) {
            float h = siluf(acc);
            g_h2silu[b * HID + o] = siluf(h);
            float u = (h - KNOT_T0) * KNOT_INVH;
            float4 ba, bb;
            ba.x = ubasis(u, 0.0f); ba.y = ubasis(u, 1.0f);
            ba.z = ubasis(u, 2.0f); ba.w = ubasis(u, 3.0f);
            bb.x = ubasis(u, 4.0f); bb.y = ubasis(u, 5.0f);
            bb.z = ubasis(u, 6.0f); bb.w = ubasis(u, 7.0f);
            g_b2[(b * HID + o) * 2]     = ba;
            g_b2[(b * HID + o) * 2 + 1] = bb;
        }
    }
}

// ---------------------------------------------------------------------------
// Kernel 3: inline gate (warp 0, hidden under x loads) + apply.
// Measured 78.9us @ 77.3% DRAM in round 16 — kept verbatim.
// ---------------------------------------------------------------------------
__global__ void __launch_bounds__(256) gate_apply_kernel(
    const float4* __restrict__ x,
    const float* __restrict__ bw2, const float* __restrict__ sw2,
    const float* __restrict__ sc2,
    float4* __restrict__ out) {

    const int lane = threadIdx.x & 31;
    const int wid  = threadIdx.x >> 5;
    const int plane = blockIdx.x;
    const int b = plane >> 9;
    const int c = plane & (CIN - 1);

    __shared__ float sh_g;

    // Issue x loads first (independent of gate computation).
    const float4* p = x + (size_t)plane * PLANE4;
    float4 v0 = p[threadIdx.x];
    float4 v1 = p[256 + threadIdx.x];
    float4 v2 = p[512 + threadIdx.x];
    float4 v3 = p[768 + threadIdx.x];

    // Warp 0 computes the gate while the x loads are in flight.
    if (wid == 0) {
        const int j0 = lane * 2;
        const float4* sw4 = (const float4*)(sw2 + (size_t)c * HID * NBASE);
        float4 w0 = sw4[j0 * 2];
        float4 w1 = sw4[j0 * 2 + 1];
        float4 w2 = sw4[j0 * 2 + 2];
        float4 w3 = sw4[j0 * 2 + 3];
        float4 c0 = g_b2[(b * HID + j0) * 2];
        float4 c1 = g_b2[(b * HID + j0) * 2 + 1];
        float4 c2 = g_b2[(b * HID + j0 + 1) * 2];
        float4 c3 = g_b2[(b * HID + j0 + 1) * 2 + 1];
        float sp0 = c0.x * w0.x + c0.y * w0.y + c0.z * w0.z + c0.w * w0.w
                  + c1.x * w1.x + c1.y * w1.y + c1.z * w1.z + c1.w * w1.w;
        float sp1 = c2.x * w2.x + c2.y * w2.y + c2.z * w2.z + c2.w * w2.w
                  + c3.x * w3.x + c3.y * w3.y + c3.z * w3.z + c3.w * w3.w;
        float2 bw = *(const float2*)(bw2 + c * HID + j0);
        float2 sc = *(const float2*)(sc2 + c * HID + j0);
        float2 h2 = *(const float2*)(g_h2silu + b * HID + j0);
        float acc = h2.x * bw.x + sp0 * sc.x + h2.y * bw.y + sp1 * sc.y;
#pragma unroll
        for (int off = 16; off >= 1; off >>= 1)
            acc += __shfl_xor_sync(0xffffffffu, acc, off);
        if (lane == 0) sh_g = 1.0f / (1.0f + __expf(-acc));
    }
    __syncthreads();
    const float g = sh_g;

    float4* q = out + (size_t)plane * PLANE4;
    v0.x *= g; v0.y *= g; v0.z *= g; v0.w *= g;
    v1.x *= g; v1.y *= g; v1.z *= g; v1.w *= g;
    v2.x *= g; v2.y *= g; v2.z *= g; v2.w *= g;
    v3.x *= g; v3.y *= g; v3.z *= g; v3.w *= g;
    __stcs(&q[threadIdx.x], v0);
    __stcs(&q[256 + threadIdx.x], v1);
    __stcs(&q[512 + threadIdx.x], v2);
    __stcs(&q[768 + threadIdx.x], v3);
}

extern "C" void kernel_launch(void* const* d_in, const int* in_sizes, int n_in,
                              void* d_out, int out_size) {
    const float* x     = (const float*)d_in[0];
    const float* bw1   = (const float*)d_in[2];
    const float* sw1   = (const float*)d_in[3];
    const float* sc1   = (const float*)d_in[4];
    const float* bw2   = (const float*)d_in[6];
    const float* sw2   = (const float*)d_in[7];
    const float* sc2   = (const float*)d_in[8];
    float* out = (float*)d_out;

    float* mean_buf;
    cudaGetSymbolAddress((void**)&mean_buf, g_mean);

    mean_kernel<<<NPLANES, 256>>>((const float4*)x, mean_buf);
    kan1_kernel<<<BATCH, 256>>>(bw1, sw1, sc1);
    gate_apply_kernel<<<NPLANES, 256>>>((const float4*)x, bw2, sw2, sc2,
                                        (float4*)out);
}